// round 8
// baseline (speedup 1.0000x reference)
#include <cuda_runtime.h>
#include <cstdint>

#define T_SEQ   2048
#define D_MODEL 1024
#define N_HEADS 16
#define D_HEAD  64
#define B_SZ    2
#define N_TOK   (B_SZ * T_SEQ)   // 4096

// Scratch (device globals: allocation-free per harness rules)
__device__ float g_qkv[(size_t)N_TOK * 3 * D_MODEL];   // [4096, 3072]
__device__ float g_attn[(size_t)N_TOK * D_MODEL];      // [4096, 1024]

// ---------------------------------------------------------------------------
// tf32 helpers
// ---------------------------------------------------------------------------
__device__ __forceinline__ uint32_t f2tf32(float x) {
    uint32_t r;
    asm("cvt.rna.tf32.f32 %0, %1;" : "=r"(r) : "f"(x));
    return r;
}

__device__ __forceinline__ void mma_tf32(float c[4], const uint32_t a[4], const uint32_t b[2]) {
    asm volatile(
        "mma.sync.aligned.m16n8k8.row.col.f32.tf32.tf32.f32 "
        "{%0,%1,%2,%3}, {%4,%5,%6,%7}, {%8,%9}, {%0,%1,%2,%3};\n"
        : "+f"(c[0]), "+f"(c[1]), "+f"(c[2]), "+f"(c[3])
        : "r"(a[0]), "r"(a[1]), "r"(a[2]), "r"(a[3]), "r"(b[0]), "r"(b[1]));
}

// ---------------------------------------------------------------------------
// tf32 tensor-core GEMM with fused bias, double-buffered smem.
// C[M,N] = A[M,K] @ B[K,N] + bias[N], row-major. M%128==0, N%128==0, K%16==0.
// Block tile 128x128, K-tile 16, 256 threads = 8 warps, warp tile 32x64.
// 2 smem stages; one __syncthreads per K-iter; LDG k+1 issued before compute k.
// Pads: LDA=20, LDB=136 -> all fragment reads bank-conflict-free.
// ---------------------------------------------------------------------------
#define LDA 20
#define LDB 136

template <int M, int N, int K>
__global__ void __launch_bounds__(256, 2) gemm_tf32_bias_kernel(
    const float* __restrict__ A, const float* __restrict__ B,
    const float* __restrict__ bias, float* __restrict__ C)
{
    __shared__ __align__(16) uint32_t As[2][128 * LDA];   // [stage][128][16] padded
    __shared__ __align__(16) uint32_t Bs[2][16 * LDB];    // [stage][16][128] padded

    const int tid  = threadIdx.x;
    const int warp = tid >> 5;
    const int lane = tid & 31;
    const int g    = lane >> 2;          // 0..7
    const int tg   = lane & 3;           // 0..3
    const int wm   = (warp >> 1) * 32;   // warp M offset: 0,32,64,96
    const int wn   = (warp & 1) * 64;    // warp N offset: 0,64

    const int bm = blockIdx.y;
    const int bn = blockIdx.x;

    const float* Ab = A + (size_t)bm * 128 * K;
    const float* Bb = B + (size_t)bn * 128;

    float acc[2][8][4];
    #pragma unroll
    for (int i = 0; i < 2; ++i)
        #pragma unroll
        for (int j = 0; j < 8; ++j)
            #pragma unroll
            for (int q = 0; q < 4; ++q) acc[i][j][q] = 0.0f;

    // ---- prologue: fill stage 0 ----
    {
        #pragma unroll
        for (int p = 0; p < 2; ++p) {
            int f  = tid + p * 256;
            int a_r = f >> 2, a_c = (f & 3) * 4;
            float4 av = *(const float4*)(Ab + (size_t)a_r * K + a_c);
            *(uint4*)(&As[0][a_r * LDA + a_c]) =
                make_uint4(f2tf32(av.x), f2tf32(av.y), f2tf32(av.z), f2tf32(av.w));
            int b_r = f >> 5, b_c = (f & 31) * 4;
            float4 bv = *(const float4*)(Bb + (size_t)b_r * N + b_c);
            *(uint4*)(&Bs[0][b_r * LDB + b_c]) =
                make_uint4(f2tf32(bv.x), f2tf32(bv.y), f2tf32(bv.z), f2tf32(bv.w));
        }
    }

    int cur = 0;
    for (int kt = 0; kt < K; kt += 16) {
        __syncthreads();   // stage `cur` fully written; prev reads of `nxt` done

        const bool has_next = (kt + 16 < K);
        float4 areg[2], breg[2];
        if (has_next) {
            #pragma unroll
            for (int p = 0; p < 2; ++p) {
                int f  = tid + p * 256;
                int a_r = f >> 2, a_c = (f & 3) * 4;
                areg[p] = *(const float4*)(Ab + (size_t)a_r * K + kt + 16 + a_c);
                int b_r = f >> 5, b_c = (f & 31) * 4;
                breg[p] = *(const float4*)(Bb + (size_t)(kt + 16 + b_r) * N + b_c);
            }
        }

        // ---- compute on stage `cur` ----
        const uint32_t* Asc = As[cur];
        const uint32_t* Bsc = Bs[cur];
        #pragma unroll
        for (int ks = 0; ks < 2; ++ks) {
            const int kk = ks * 8;
            uint32_t a[2][4], b[8][2];
            #pragma unroll
            for (int mm = 0; mm < 2; ++mm) {
                const int r0 = wm + mm * 16;
                a[mm][0] = Asc[(r0 + g)     * LDA + kk + tg];
                a[mm][1] = Asc[(r0 + g + 8) * LDA + kk + tg];
                a[mm][2] = Asc[(r0 + g)     * LDA + kk + tg + 4];
                a[mm][3] = Asc[(r0 + g + 8) * LDA + kk + tg + 4];
            }
            #pragma unroll
            for (int nn = 0; nn < 8; ++nn) {
                const int c0 = wn + nn * 8 + g;
                b[nn][0] = Bsc[(kk + tg)     * LDB + c0];
                b[nn][1] = Bsc[(kk + tg + 4) * LDB + c0];
            }
            #pragma unroll
            for (int mm = 0; mm < 2; ++mm)
                #pragma unroll
                for (int nn = 0; nn < 8; ++nn)
                    mma_tf32(acc[mm][nn], a[mm], b[nn]);
        }

        // ---- fill stage `nxt` (LDGs have had the whole mma block to land) ----
        if (has_next) {
            const int nxt = cur ^ 1;
            #pragma unroll
            for (int p = 0; p < 2; ++p) {
                int f  = tid + p * 256;
                int a_r = f >> 2, a_c = (f & 3) * 4;
                *(uint4*)(&As[nxt][a_r * LDA + a_c]) =
                    make_uint4(f2tf32(areg[p].x), f2tf32(areg[p].y),
                               f2tf32(areg[p].z), f2tf32(areg[p].w));
                int b_r = f >> 5, b_c = (f & 31) * 4;
                *(uint4*)(&Bs[nxt][b_r * LDB + b_c]) =
                    make_uint4(f2tf32(breg[p].x), f2tf32(breg[p].y),
                               f2tf32(breg[p].z), f2tf32(breg[p].w));
            }
        }
        cur ^= 1;
    }

    // ---- epilogue: bias + store ----
    #pragma unroll
    for (int mm = 0; mm < 2; ++mm) {
        const int r0 = bm * 128 + wm + mm * 16 + g;
        #pragma unroll
        for (int nn = 0; nn < 8; ++nn) {
            const int c0g = bn * 128 + wn + nn * 8 + 2 * tg;
            float b0 = bias[c0g], b1 = bias[c0g + 1];
            float2 v0 = make_float2(acc[mm][nn][0] + b0, acc[mm][nn][1] + b1);
            float2 v1 = make_float2(acc[mm][nn][2] + b0, acc[mm][nn][3] + b1);
            *(float2*)(C + (size_t)r0 * N + c0g)       = v0;
            *(float2*)(C + (size_t)(r0 + 8) * N + c0g) = v1;
        }
    }
}

// ---------------------------------------------------------------------------
// Causal flash attention on tf32 tensor cores (unchanged from round 5).
// 128 threads = 4 warps. Q-tile 64 (16 rows/warp), K-tile 64, DH=64.
// ---------------------------------------------------------------------------
__global__ void __launch_bounds__(128, 2) flash_attn_tc_kernel()
{
    __shared__ __align__(16) uint32_t KP[64 * 68];   // K tile / Q staging / P bounce
    __shared__ __align__(16) uint32_t Vs[64 * 72];   // V tile

    const int tid  = threadIdx.x;
    const int warp = tid >> 5;
    const int lane = tid & 31;
    const int g    = lane >> 2;
    const int tg   = lane & 3;
    const int qt   = gridDim.x - 1 - blockIdx.x;
    const int h    = blockIdx.y;
    const int b    = blockIdx.z;
    const int q0   = qt * 64;
    const int qrow = warp * 16;

    const float* qkv = g_qkv;

    #pragma unroll
    for (int p = 0; p < 8; ++p) {
        int idx = tid + p * 128;
        int r = idx >> 4, c = (idx & 15) * 4;
        float4 v = *(const float4*)(qkv + (size_t)(b * T_SEQ + q0 + r) * 3072 + h * 64 + c);
        *(uint4*)(KP + r * 68 + c) =
            make_uint4(f2tf32(v.x), f2tf32(v.y), f2tf32(v.z), f2tf32(v.w));
    }
    __syncthreads();

    uint32_t aq[8][4];
    #pragma unroll
    for (int d0 = 0; d0 < 8; ++d0) {
        aq[d0][0] = KP[(qrow + g)     * 68 + d0 * 8 + tg];
        aq[d0][1] = KP[(qrow + g + 8) * 68 + d0 * 8 + tg];
        aq[d0][2] = KP[(qrow + g)     * 68 + d0 * 8 + tg + 4];
        aq[d0][3] = KP[(qrow + g + 8) * 68 + d0 * 8 + tg + 4];
    }

    float oacc[8][4];
    #pragma unroll
    for (int i = 0; i < 8; ++i)
        #pragma unroll
        for (int j = 0; j < 4; ++j) oacc[i][j] = 0.0f;
    float mrow0 = -1e30f, mrow1 = -1e30f;
    float lrow0 = 0.0f,   lrow1 = 0.0f;

    const int nkt = qt + 1;
    for (int kt = 0; kt < nkt; ++kt) {
        const int k0 = kt * 64;

        __syncthreads();

        #pragma unroll
        for (int p = 0; p < 8; ++p) {
            int idx = tid + p * 128;
            int r = idx >> 4, c = (idx & 15) * 4;
            const float* base = qkv + (size_t)(b * T_SEQ + k0 + r) * 3072 + h * 64 + c;
            float4 kv = *(const float4*)(base + 1024);
            float4 vv = *(const float4*)(base + 2048);
            *(uint4*)(KP + r * 68 + c) =
                make_uint4(f2tf32(kv.x), f2tf32(kv.y), f2tf32(kv.z), f2tf32(kv.w));
            *(uint4*)(Vs + r * 72 + c) =
                make_uint4(f2tf32(vv.x), f2tf32(vv.y), f2tf32(vv.z), f2tf32(vv.w));
        }
        __syncthreads();

        float sacc[8][4];
        #pragma unroll
        for (int i = 0; i < 8; ++i)
            #pragma unroll
            for (int j = 0; j < 4; ++j) sacc[i][j] = 0.0f;

        #pragma unroll
        for (int n0 = 0; n0 < 8; ++n0) {
            #pragma unroll
            for (int d0 = 0; d0 < 8; ++d0) {
                uint32_t bf[2] = { KP[(n0 * 8 + g) * 68 + d0 * 8 + tg],
                                   KP[(n0 * 8 + g) * 68 + d0 * 8 + tg + 4] };
                mma_tf32(sacc[n0], aq[d0], bf);
            }
        }

        const int row0 = q0 + qrow + g;
        const int row1 = row0 + 8;
        const bool domask = (k0 + 63 > q0 + qrow);
        float ml0 = -1e30f, ml1 = -1e30f;
        #pragma unroll
        for (int n0 = 0; n0 < 8; ++n0) {
            const int c0 = k0 + n0 * 8 + 2 * tg;
            const int c1 = c0 + 1;
            float s0 = sacc[n0][0] * 0.125f;
            float s1 = sacc[n0][1] * 0.125f;
            float s2 = sacc[n0][2] * 0.125f;
            float s3 = sacc[n0][3] * 0.125f;
            if (domask) {
                if (c0 > row0) s0 = -1e30f;
                if (c1 > row0) s1 = -1e30f;
                if (c0 > row1) s2 = -1e30f;
                if (c1 > row1) s3 = -1e30f;
            }
            sacc[n0][0] = s0; sacc[n0][1] = s1;
            sacc[n0][2] = s2; sacc[n0][3] = s3;
            ml0 = fmaxf(ml0, fmaxf(s0, s1));
            ml1 = fmaxf(ml1, fmaxf(s2, s3));
        }
        ml0 = fmaxf(ml0, __shfl_xor_sync(0xffffffffu, ml0, 1));
        ml0 = fmaxf(ml0, __shfl_xor_sync(0xffffffffu, ml0, 2));
        ml1 = fmaxf(ml1, __shfl_xor_sync(0xffffffffu, ml1, 1));
        ml1 = fmaxf(ml1, __shfl_xor_sync(0xffffffffu, ml1, 2));

        const float nm0 = fmaxf(mrow0, ml0);
        const float nm1 = fmaxf(mrow1, ml1);
        const float al0 = __expf(mrow0 - nm0);
        const float al1 = __expf(mrow1 - nm1);
        mrow0 = nm0; mrow1 = nm1;

        float sum0 = 0.0f, sum1 = 0.0f;
        #pragma unroll
        for (int n0 = 0; n0 < 8; ++n0) {
            float p0 = __expf(sacc[n0][0] - nm0);
            float p1 = __expf(sacc[n0][1] - nm0);
            float p2 = __expf(sacc[n0][2] - nm1);
            float p3 = __expf(sacc[n0][3] - nm1);
            sacc[n0][0] = p0; sacc[n0][1] = p1;
            sacc[n0][2] = p2; sacc[n0][3] = p3;
            sum0 += p0 + p1;
            sum1 += p2 + p3;
        }
        sum0 += __shfl_xor_sync(0xffffffffu, sum0, 1);
        sum0 += __shfl_xor_sync(0xffffffffu, sum0, 2);
        sum1 += __shfl_xor_sync(0xffffffffu, sum1, 1);
        sum1 += __shfl_xor_sync(0xffffffffu, sum1, 2);
        lrow0 = lrow0 * al0 + sum0;
        lrow1 = lrow1 * al1 + sum1;

        #pragma unroll
        for (int n0 = 0; n0 < 8; ++n0) {
            oacc[n0][0] *= al0; oacc[n0][1] *= al0;
            oacc[n0][2] *= al1; oacc[n0][3] *= al1;
        }

        __syncthreads();
        #pragma unroll
        for (int n0 = 0; n0 < 8; ++n0) {
            *(uint2*)(KP + (qrow + g)     * 68 + n0 * 8 + 2 * tg) =
                make_uint2(f2tf32(sacc[n0][0]), f2tf32(sacc[n0][1]));
            *(uint2*)(KP + (qrow + g + 8) * 68 + n0 * 8 + 2 * tg) =
                make_uint2(f2tf32(sacc[n0][2]), f2tf32(sacc[n0][3]));
        }
        __syncwarp();

        uint32_t ap[8][4];
        #pragma unroll
        for (int kc = 0; kc < 8; ++kc) {
            ap[kc][0] = KP[(qrow + g)     * 68 + kc * 8 + tg];
            ap[kc][1] = KP[(qrow + g + 8) * 68 + kc * 8 + tg];
            ap[kc][2] = KP[(qrow + g)     * 68 + kc * 8 + tg + 4];
            ap[kc][3] = KP[(qrow + g + 8) * 68 + kc * 8 + tg + 4];
        }

        #pragma unroll
        for (int n0 = 0; n0 < 8; ++n0) {
            #pragma unroll
            for (int kc = 0; kc < 8; ++kc) {
                uint32_t bf[2] = { Vs[(kc * 8 + tg)     * 72 + n0 * 8 + g],
                                   Vs[(kc * 8 + tg + 4) * 72 + n0 * 8 + g] };
                mma_tf32(oacc[n0], ap[kc], bf);
            }
        }
    }

    const float li0 = 1.0f / lrow0;
    const float li1 = 1.0f / lrow1;
    const size_t grow0 = (size_t)(b * T_SEQ + q0 + qrow + g);
    const size_t grow1 = grow0 + 8;
    #pragma unroll
    for (int n0 = 0; n0 < 8; ++n0) {
        const int col = h * 64 + n0 * 8 + 2 * tg;
        *(float2*)(g_attn + grow0 * D_MODEL + col) =
            make_float2(oacc[n0][0] * li0, oacc[n0][1] * li0);
        *(float2*)(g_attn + grow1 * D_MODEL + col) =
            make_float2(oacc[n0][2] * li1, oacc[n0][3] * li1);
    }
}

// ---------------------------------------------------------------------------
// Harness entry. Inputs: x, w_qkv, b_qkv, w_out, b_out (all fp32).
// ---------------------------------------------------------------------------
extern "C" void kernel_launch(void* const* d_in, const int* in_sizes, int n_in,
                              void* d_out, int out_size)
{
    (void)in_sizes; (void)n_in; (void)out_size;
    const float* x     = (const float*)d_in[0];
    const float* w_qkv = (const float*)d_in[1];
    const float* b_qkv = (const float*)d_in[2];
    const float* w_out = (const float*)d_in[3];
    const float* b_out = (const float*)d_in[4];
    float* out = (float*)d_out;

    float* qkv_buf  = nullptr;
    float* attn_buf = nullptr;
    cudaGetSymbolAddress((void**)&qkv_buf, g_qkv);
    cudaGetSymbolAddress((void**)&attn_buf, g_attn);

    // 1) QKV projection: [4096,1024] @ [1024,3072] + b
    gemm_tf32_bias_kernel<N_TOK, 3 * D_MODEL, D_MODEL>
        <<<dim3((3 * D_MODEL) / 128, N_TOK / 128), 256>>>(x, w_qkv, b_qkv, qkv_buf);

    // 2) causal flash attention (tensor cores) -> [B, T, H*DH]
    flash_attn_tc_kernel<<<dim3(T_SEQ / 64, N_HEADS, B_SZ), 128>>>();

    // 3) output projection: [4096,1024] @ [1024,1024] + b
    gemm_tf32_bias_kernel<N_TOK, D_MODEL, D_MODEL>
        <<<dim3(D_MODEL / 128, N_TOK / 128), 256>>>(attn_buf, w_out, b_out, out);
}

// round 10
// speedup vs baseline: 1.4016x; 1.4016x over previous
#include <cuda_runtime.h>
#include <cuda_fp16.h>
#include <cstdint>

#define T_SEQ   2048
#define D_MODEL 1024
#define N_HEADS 16
#define D_HEAD  64
#define B_SZ    2
#define N_TOK   (B_SZ * T_SEQ)   // 4096

// Scratch (device globals: allocation-free per harness rules)
__device__ float g_qkv[(size_t)N_TOK * 3 * D_MODEL];   // [4096, 3072]
__device__ float g_attn[(size_t)N_TOK * D_MODEL];      // [4096, 1024]

// ---------------------------------------------------------------------------
// fp16 helpers
// ---------------------------------------------------------------------------
// pack two fp32 -> f16x2 (lo in low 16 bits)
__device__ __forceinline__ uint32_t pack_f16x2(float lo, float hi) {
    uint32_t r;
    asm("cvt.rn.f16x2.f32 %0, %1, %2;" : "=r"(r) : "f"(hi), "f"(lo));
    return r;
}
// merge two zero-extended 16-bit values: lo | (hi << 16)
__device__ __forceinline__ uint32_t mrg16(uint32_t lo, uint32_t hi) {
    return __byte_perm(lo, hi, 0x5410);
}

__device__ __forceinline__ void mma_f16(float c[4], const uint32_t a[4], const uint32_t b[2]) {
    asm volatile(
        "mma.sync.aligned.m16n8k16.row.col.f32.f16.f16.f32 "
        "{%0,%1,%2,%3}, {%4,%5,%6,%7}, {%8,%9}, {%0,%1,%2,%3};\n"
        : "+f"(c[0]), "+f"(c[1]), "+f"(c[2]), "+f"(c[3])
        : "r"(a[0]), "r"(a[1]), "r"(a[2]), "r"(a[3]), "r"(b[0]), "r"(b[1]));
}

// ---------------------------------------------------------------------------
// fp16 tensor-core GEMM with fused bias, double-buffered smem.
// C[M,N] = A[M,K] @ B[K,N] + bias[N], row-major. M%128==0, N%128==0, K%16==0.
// Block tile 128x128, ktile 16, 256 threads = 8 warps, warp tile 32x64.
// A smem: [128 r][8 kpairs] words, pad GLDA=12 (frag reads 12g+tg: conflict-free).
// B smem: [16 k][128 n] fp16 halves, row 66 words; B-frags = 2x LDS.U16 + PRMT
// (16 distinct words x 2-lane broadcast: conflict-free).
// ---------------------------------------------------------------------------
#define GLDA 12
#define GLDB 66    // words per B row (64 data + 2 pad)

template <int M, int N, int K>
__global__ void __launch_bounds__(256, 2) gemm_f16_kernel(
    const float* __restrict__ A, const float* __restrict__ B,
    const float* __restrict__ bias, float* __restrict__ C)
{
    __shared__ __align__(16) uint32_t As[2][128 * GLDA];   // 6 KB/stage
    __shared__ __align__(16) uint32_t Bs[2][16 * GLDB];    // 4.125 KB/stage

    const int tid  = threadIdx.x;
    const int warp = tid >> 5;
    const int lane = tid & 31;
    const int g    = lane >> 2;          // 0..7
    const int tg   = lane & 3;           // 0..3
    const int wm   = (warp >> 1) * 32;   // warp M offset: 0,32,64,96
    const int wn   = (warp & 1) * 64;    // warp N offset: 0,64

    const int bm = blockIdx.y;
    const int bn = blockIdx.x;

    const float* Ab = A + (size_t)bm * 128 * K;
    const float* Bb = B + (size_t)bn * 128;

    float acc[2][8][4];
    #pragma unroll
    for (int i = 0; i < 2; ++i)
        #pragma unroll
        for (int j = 0; j < 8; ++j)
            #pragma unroll
            for (int q = 0; q < 4; ++q) acc[i][j][q] = 0.0f;

    // ---- prologue: fill stage 0 ----
    #pragma unroll
    for (int p = 0; p < 2; ++p) {
        int f  = tid + p * 256;                       // 0..511
        int ar = f >> 2, ac4 = f & 3;                 // A: row, float4 idx
        float4 av = *(const float4*)(Ab + (size_t)ar * K + ac4 * 4);
        *(uint2*)(&As[0][ar * GLDA + 2 * ac4]) =
            make_uint2(pack_f16x2(av.x, av.y), pack_f16x2(av.z, av.w));
        int kr = f >> 5, cw = f & 31;                 // B: k row, float4 idx
        float4 bv = *(const float4*)(Bb + (size_t)kr * N + cw * 4);
        *(uint2*)(&Bs[0][kr * GLDB + 2 * cw]) =
            make_uint2(pack_f16x2(bv.x, bv.y), pack_f16x2(bv.z, bv.w));
    }

    int cur = 0;
    for (int kt = 0; kt < K; kt += 16) {
        __syncthreads();   // stage `cur` written; prev reads of `nxt` done

        const bool has_next = (kt + 16 < K);
        float4 areg[2], breg[2];
        if (has_next) {
            #pragma unroll
            for (int p = 0; p < 2; ++p) {
                int f  = tid + p * 256;
                int ar = f >> 2, ac4 = f & 3;
                areg[p] = *(const float4*)(Ab + (size_t)ar * K + kt + 16 + ac4 * 4);
                int kr = f >> 5, cw = f & 31;
                breg[p] = *(const float4*)(Bb + (size_t)(kt + 16 + kr) * N + cw * 4);
            }
        }

        // ---- compute on stage `cur` (one k16 step) ----
        const uint32_t* Asc = As[cur];
        const uint16_t* Bh  = (const uint16_t*)Bs[cur];   // half idx = k*132 + n
        {
            uint32_t a[2][4], b[8][2];
            #pragma unroll
            for (int mm = 0; mm < 2; ++mm) {
                const int r0 = wm + mm * 16;
                a[mm][0] = Asc[(r0 + g)     * GLDA + tg];
                a[mm][1] = Asc[(r0 + g + 8) * GLDA + tg];
                a[mm][2] = Asc[(r0 + g)     * GLDA + tg + 4];
                a[mm][3] = Asc[(r0 + g + 8) * GLDA + tg + 4];
            }
            #pragma unroll
            for (int nn = 0; nn < 8; ++nn) {
                const int c0 = wn + nn * 8 + g;
                b[nn][0] = mrg16(Bh[(2 * tg)     * 132 + c0],
                                 Bh[(2 * tg + 1) * 132 + c0]);
                b[nn][1] = mrg16(Bh[(2 * tg + 8) * 132 + c0],
                                 Bh[(2 * tg + 9) * 132 + c0]);
            }
            #pragma unroll
            for (int mm = 0; mm < 2; ++mm)
                #pragma unroll
                for (int nn = 0; nn < 8; ++nn)
                    mma_f16(acc[mm][nn], a[mm], b[nn]);
        }

        // ---- fill stage `nxt` ----
        if (has_next) {
            const int nxt = cur ^ 1;
            #pragma unroll
            for (int p = 0; p < 2; ++p) {
                int f  = tid + p * 256;
                int ar = f >> 2, ac4 = f & 3;
                *(uint2*)(&As[nxt][ar * GLDA + 2 * ac4]) =
                    make_uint2(pack_f16x2(areg[p].x, areg[p].y),
                               pack_f16x2(areg[p].z, areg[p].w));
                int kr = f >> 5, cw = f & 31;
                *(uint2*)(&Bs[nxt][kr * GLDB + 2 * cw]) =
                    make_uint2(pack_f16x2(breg[p].x, breg[p].y),
                               pack_f16x2(breg[p].z, breg[p].w));
            }
        }
        cur ^= 1;
    }

    // ---- epilogue: bias + store (C-frag: c0,c1 @ (g,2tg); c2,c3 @ (g+8,2tg)) ----
    #pragma unroll
    for (int mm = 0; mm < 2; ++mm) {
        const int r0 = bm * 128 + wm + mm * 16 + g;
        #pragma unroll
        for (int nn = 0; nn < 8; ++nn) {
            const int c0g = bn * 128 + wn + nn * 8 + 2 * tg;
            float b0 = bias[c0g], b1 = bias[c0g + 1];
            float2 v0 = make_float2(acc[mm][nn][0] + b0, acc[mm][nn][1] + b1);
            float2 v1 = make_float2(acc[mm][nn][2] + b0, acc[mm][nn][3] + b1);
            *(float2*)(C + (size_t)r0 * N + c0g)       = v0;
            *(float2*)(C + (size_t)(r0 + 8) * N + c0g) = v1;
        }
    }
}

// ---------------------------------------------------------------------------
// Causal flash attention on fp16 tensor cores (m16n8k16).
// 128 threads = 4 warps. Q-tile 64 (16 rows/warp), K-tile 64, DH=64.
// Q pre-scaled by 1/8, resident as A-frags. K: [token][dpair] words (pad 36,
// frag reads 36g+tg ≡ 4g+tg: conflict-free). V: [token][d] fp16 halves
// (row 72 halves); V-frags via 2x LDS.U16 + PRMT (broadcast pairs).
// P: C-frag -> A-frag IN REGISTERS (no smem bounce, no extra sync).
// ---------------------------------------------------------------------------
#define FLK 36    // words per K/Q row (32 pairs + 4 pad)
#define FLV 36    // words per V row (32 data + 4 pad); halves stride 72

__global__ void __launch_bounds__(128, 3) flash_attn_f16_kernel()
{
    __shared__ __align__(16) uint32_t Ks[64 * FLK];   // Q staging, then K tiles
    __shared__ __align__(16) uint32_t Vs[64 * FLV];   // V tiles (fp16 halves)

    const int tid  = threadIdx.x;
    const int warp = tid >> 5;
    const int lane = tid & 31;
    const int g    = lane >> 2;     // 0..7
    const int tg   = lane & 3;      // 0..3
    const int qt   = gridDim.x - 1 - blockIdx.x;   // long diagonals first
    const int h    = blockIdx.y;
    const int b    = blockIdx.z;
    const int q0   = qt * 64;
    const int qrow = warp * 16;

    const float* qkv = g_qkv;

    // ---- stage Q (scaled by 1/8) into Ks; extract persistent A-frags ----
    #pragma unroll
    for (int p = 0; p < 8; ++p) {
        int idx = tid + p * 128;
        int r = idx >> 4, cp = idx & 15;             // float4 index 0..15
        float4 v = *(const float4*)(qkv + (size_t)(b * T_SEQ + q0 + r) * 3072 + h * 64 + cp * 4);
        *(uint2*)(&Ks[r * FLK + 2 * cp]) =
            make_uint2(pack_f16x2(v.x * 0.125f, v.y * 0.125f),
                       pack_f16x2(v.z * 0.125f, v.w * 0.125f));
    }
    __syncthreads();

    uint32_t aq[4][4];   // kc chunk = d 16kc..16kc+15 = pairs 8kc..8kc+7
    #pragma unroll
    for (int kc = 0; kc < 4; ++kc) {
        aq[kc][0] = Ks[(qrow + g)     * FLK + 8 * kc + tg];
        aq[kc][1] = Ks[(qrow + g + 8) * FLK + 8 * kc + tg];
        aq[kc][2] = Ks[(qrow + g)     * FLK + 8 * kc + tg + 4];
        aq[kc][3] = Ks[(qrow + g + 8) * FLK + 8 * kc + tg + 4];
    }

    float oacc[8][4];
    #pragma unroll
    for (int i = 0; i < 8; ++i)
        #pragma unroll
        for (int j = 0; j < 4; ++j) oacc[i][j] = 0.0f;
    float mrow0 = -1e30f, mrow1 = -1e30f;
    float lrow0 = 0.0f,   lrow1 = 0.0f;

    const int nkt = qt + 1;
    for (int kt = 0; kt < nkt; ++kt) {
        const int k0 = kt * 64;

        __syncthreads();   // prior-iteration K/V reads (and aq extraction) done

        // ---- load K, V tiles as fp16 ----
        #pragma unroll
        for (int p = 0; p < 8; ++p) {
            int idx = tid + p * 128;
            int r = idx >> 4, cp = idx & 15;
            const float* base = qkv + (size_t)(b * T_SEQ + k0 + r) * 3072 + h * 64 + cp * 4;
            float4 kv = *(const float4*)(base + 1024);
            float4 vv = *(const float4*)(base + 2048);
            *(uint2*)(&Ks[r * FLK + 2 * cp]) =
                make_uint2(pack_f16x2(kv.x, kv.y), pack_f16x2(kv.z, kv.w));
            *(uint2*)(&Vs[r * FLV + 2 * cp]) =
                make_uint2(pack_f16x2(vv.x, vv.y), pack_f16x2(vv.z, vv.w));
        }
        __syncthreads();

        // ---- S = Q @ K^T  (per warp: 16x64, 32 mmas) ----
        float sacc[8][4];
        #pragma unroll
        for (int i = 0; i < 8; ++i)
            #pragma unroll
            for (int j = 0; j < 4; ++j) sacc[i][j] = 0.0f;

        #pragma unroll
        for (int n0 = 0; n0 < 8; ++n0) {
            const int krow = (n0 * 8 + g) * FLK;
            #pragma unroll
            for (int kc = 0; kc < 4; ++kc) {
                uint32_t bf[2] = { Ks[krow + 8 * kc + tg],
                                   Ks[krow + 8 * kc + tg + 4] };
                mma_f16(sacc[n0], aq[kc], bf);
            }
        }

        // ---- causal mask + row max (scale already folded into Q) ----
        const int row0 = q0 + qrow + g;
        const int row1 = row0 + 8;
        const bool domask = (k0 + 63 > q0 + qrow);
        float ml0 = -1e30f, ml1 = -1e30f;
        #pragma unroll
        for (int n0 = 0; n0 < 8; ++n0) {
            const int c0 = k0 + n0 * 8 + 2 * tg;
            const int c1 = c0 + 1;
            float s0 = sacc[n0][0];
            float s1 = sacc[n0][1];
            float s2 = sacc[n0][2];
            float s3 = sacc[n0][3];
            if (domask) {
                if (c0 > row0) s0 = -1e30f;
                if (c1 > row0) s1 = -1e30f;
                if (c0 > row1) s2 = -1e30f;
                if (c1 > row1) s3 = -1e30f;
            }
            sacc[n0][0] = s0; sacc[n0][1] = s1;
            sacc[n0][2] = s2; sacc[n0][3] = s3;
            ml0 = fmaxf(ml0, fmaxf(s0, s1));
            ml1 = fmaxf(ml1, fmaxf(s2, s3));
        }
        ml0 = fmaxf(ml0, __shfl_xor_sync(0xffffffffu, ml0, 1));
        ml0 = fmaxf(ml0, __shfl_xor_sync(0xffffffffu, ml0, 2));
        ml1 = fmaxf(ml1, __shfl_xor_sync(0xffffffffu, ml1, 1));
        ml1 = fmaxf(ml1, __shfl_xor_sync(0xffffffffu, ml1, 2));

        const float nm0 = fmaxf(mrow0, ml0);
        const float nm1 = fmaxf(mrow1, ml1);
        const float al0 = __expf(mrow0 - nm0);
        const float al1 = __expf(mrow1 - nm1);
        mrow0 = nm0; mrow1 = nm1;

        // ---- P = exp(S - m), row sums ----
        float sum0 = 0.0f, sum1 = 0.0f;
        #pragma unroll
        for (int n0 = 0; n0 < 8; ++n0) {
            float p0 = __expf(sacc[n0][0] - nm0);
            float p1 = __expf(sacc[n0][1] - nm0);
            float p2 = __expf(sacc[n0][2] - nm1);
            float p3 = __expf(sacc[n0][3] - nm1);
            sacc[n0][0] = p0; sacc[n0][1] = p1;
            sacc[n0][2] = p2; sacc[n0][3] = p3;
            sum0 += p0 + p1;
            sum1 += p2 + p3;
        }
        sum0 += __shfl_xor_sync(0xffffffffu, sum0, 1);
        sum0 += __shfl_xor_sync(0xffffffffu, sum0, 2);
        sum1 += __shfl_xor_sync(0xffffffffu, sum1, 1);
        sum1 += __shfl_xor_sync(0xffffffffu, sum1, 2);
        lrow0 = lrow0 * al0 + sum0;
        lrow1 = lrow1 * al1 + sum1;

        #pragma unroll
        for (int n0 = 0; n0 < 8; ++n0) {
            oacc[n0][0] *= al0; oacc[n0][1] *= al0;
            oacc[n0][2] *= al1; oacc[n0][3] *= al1;
        }

        // ---- P: C-frag -> A-frag in registers (no smem bounce) ----
        uint32_t ap[4][4];
        #pragma unroll
        for (int kc = 0; kc < 4; ++kc) {
            ap[kc][0] = pack_f16x2(sacc[2 * kc][0],     sacc[2 * kc][1]);
            ap[kc][1] = pack_f16x2(sacc[2 * kc][2],     sacc[2 * kc][3]);
            ap[kc][2] = pack_f16x2(sacc[2 * kc + 1][0], sacc[2 * kc + 1][1]);
            ap[kc][3] = pack_f16x2(sacc[2 * kc + 1][2], sacc[2 * kc + 1][3]);
        }

        // ---- O += P @ V (V-frags: pairs along token via 2x LDS.U16 + PRMT) ----
        const uint16_t* Vh = (const uint16_t*)Vs;   // half idx = token*72 + d
        #pragma unroll
        for (int n0 = 0; n0 < 8; ++n0) {
            const int dc = n0 * 8 + g;
            #pragma unroll
            for (int kc = 0; kc < 4; ++kc) {
                const int t0 = 16 * kc + 2 * tg;
                uint32_t bf[2] = {
                    mrg16(Vh[t0 * 72 + dc],       Vh[(t0 + 1) * 72 + dc]),
                    mrg16(Vh[(t0 + 8) * 72 + dc], Vh[(t0 + 9) * 72 + dc])
                };
                mma_f16(oacc[n0], ap[kc], bf);
            }
        }
    }

    // ---- epilogue: normalize, write [B*T, D_MODEL] ----
    const float li0 = 1.0f / lrow0;
    const float li1 = 1.0f / lrow1;
    const size_t grow0 = (size_t)(b * T_SEQ + q0 + qrow + g);
    const size_t grow1 = grow0 + 8;
    #pragma unroll
    for (int n0 = 0; n0 < 8; ++n0) {
        const int col = h * 64 + n0 * 8 + 2 * tg;
        *(float2*)(g_attn + grow0 * D_MODEL + col) =
            make_float2(oacc[n0][0] * li0, oacc[n0][1] * li0);
        *(float2*)(g_attn + grow1 * D_MODEL + col) =
            make_float2(oacc[n0][2] * li1, oacc[n0][3] * li1);
    }
}

// ---------------------------------------------------------------------------
// Harness entry. Inputs: x, w_qkv, b_qkv, w_out, b_out (all fp32).
// ---------------------------------------------------------------------------
extern "C" void kernel_launch(void* const* d_in, const int* in_sizes, int n_in,
                              void* d_out, int out_size)
{
    (void)in_sizes; (void)n_in; (void)out_size;
    const float* x     = (const float*)d_in[0];
    const float* w_qkv = (const float*)d_in[1];
    const float* b_qkv = (const float*)d_in[2];
    const float* w_out = (const float*)d_in[3];
    const float* b_out = (const float*)d_in[4];
    float* out = (float*)d_out;

    float* qkv_buf  = nullptr;
    float* attn_buf = nullptr;
    cudaGetSymbolAddress((void**)&qkv_buf, g_qkv);
    cudaGetSymbolAddress((void**)&attn_buf, g_attn);

    // 1) QKV projection: [4096,1024] @ [1024,3072] + b
    gemm_f16_kernel<N_TOK, 3 * D_MODEL, D_MODEL>
        <<<dim3((3 * D_MODEL) / 128, N_TOK / 128), 256>>>(x, w_qkv, b_qkv, qkv_buf);

    // 2) causal flash attention (fp16 tensor cores) -> [B, T, H*DH]
    flash_attn_f16_kernel<<<dim3(T_SEQ / 64, N_HEADS, B_SZ), 128>>>();

    // 3) output projection: [4096,1024] @ [1024,1024] + b
    gemm_f16_kernel<N_TOK, D_MODEL, D_MODEL>
        <<<dim3(D_MODEL / 128, N_TOK / 128), 256>>>(attn_buf, w_out, b_out, out);
}

// round 12
// speedup vs baseline: 1.8095x; 1.2910x over previous
#include <cuda_runtime.h>
#include <cuda_fp16.h>
#include <cstdint>

#define T_SEQ   2048
#define D_MODEL 1024
#define N_HEADS 16
#define D_HEAD  64
#define B_SZ    2
#define N_TOK   (B_SZ * T_SEQ)   // 4096

// Scratch (device globals: allocation-free per harness rules)
__device__ float g_qkv[(size_t)N_TOK * 3 * D_MODEL];   // [4096, 3072]
__device__ float g_attn[(size_t)N_TOK * D_MODEL];      // [4096, 1024]

// ---------------------------------------------------------------------------
// fp16 / ldmatrix helpers
// ---------------------------------------------------------------------------
__device__ __forceinline__ uint32_t pack_f16x2(float lo, float hi) {
    uint32_t r;
    asm("cvt.rn.f16x2.f32 %0, %1, %2;" : "=r"(r) : "f"(hi), "f"(lo));
    return r;
}

__device__ __forceinline__ void mma_f16(float c[4], const uint32_t a[4], const uint32_t b[2]) {
    asm volatile(
        "mma.sync.aligned.m16n8k16.row.col.f32.f16.f16.f32 "
        "{%0,%1,%2,%3}, {%4,%5,%6,%7}, {%8,%9}, {%0,%1,%2,%3};\n"
        : "+f"(c[0]), "+f"(c[1]), "+f"(c[2]), "+f"(c[3])
        : "r"(a[0]), "r"(a[1]), "r"(a[2]), "r"(a[3]), "r"(b[0]), "r"(b[1]));
}

__device__ __forceinline__ uint32_t smem_u32(const void* p) {
    uint32_t a;
    asm("{ .reg .u64 t; cvta.to.shared.u64 t, %1; cvt.u32.u64 %0, t; }"
        : "=r"(a) : "l"(p));
    return a;
}

__device__ __forceinline__ void ldsm_x4(uint32_t& r0, uint32_t& r1,
                                        uint32_t& r2, uint32_t& r3, uint32_t addr) {
    asm volatile("ldmatrix.sync.aligned.m8n8.x4.shared.b16 {%0,%1,%2,%3}, [%4];"
                 : "=r"(r0), "=r"(r1), "=r"(r2), "=r"(r3) : "r"(addr));
}
__device__ __forceinline__ void ldsm_x4_t(uint32_t& r0, uint32_t& r1,
                                          uint32_t& r2, uint32_t& r3, uint32_t addr) {
    asm volatile("ldmatrix.sync.aligned.m8n8.x4.trans.shared.b16 {%0,%1,%2,%3}, [%4];"
                 : "=r"(r0), "=r"(r1), "=r"(r2), "=r"(r3) : "r"(addr));
}

// ---------------------------------------------------------------------------
// fp16 tensor-core GEMM with fused bias, double-buffered smem, ldmatrix frags.
// C[M,N] = A[M,K] @ B[K,N] + bias[N], row-major. M%128==0, N%128==0, K%16==0.
// Block tile 128x128, ktile 16, 256 threads = 8 warps, warp tile 32x64.
// A smem: [128 r][16 halves], row stride 48B (16B-aligned; ldmatrix phases
//   conflict-free: banks 12r mod 32 distinct over 8 rows).
// B smem: [16 k][128 n] halves, row stride 272B (phases: banks 4k distinct).
// A-frags: ldmatrix.x4; B-frags: ldmatrix.x4.trans.
// ---------------------------------------------------------------------------
#define GWA 12   // A row stride in words (48B)
#define GWB 68   // B row stride in words (272B)

template <int M, int N, int K>
__global__ void __launch_bounds__(256, 2) gemm_f16_kernel(
    const float* __restrict__ A, const float* __restrict__ B,
    const float* __restrict__ bias, float* __restrict__ C)
{
    __shared__ __align__(16) uint32_t As[2][128 * GWA];   // 6 KB/stage
    __shared__ __align__(16) uint32_t Bs[2][16 * GWB];    // 4.25 KB/stage

    const int tid  = threadIdx.x;
    const int warp = tid >> 5;
    const int lane = tid & 31;
    const int g    = lane >> 2;          // 0..7
    const int tg   = lane & 3;           // 0..3
    const int wm   = (warp >> 1) * 32;   // warp M offset: 0,32,64,96
    const int wn   = (warp & 1) * 64;    // warp N offset: 0,64

    const int bm = blockIdx.y;
    const int bn = blockIdx.x;

    const float* Ab = A + (size_t)bm * 128 * K;
    const float* Bb = B + (size_t)bn * 128;

    float acc[2][8][4];
    #pragma unroll
    for (int i = 0; i < 2; ++i)
        #pragma unroll
        for (int j = 0; j < 8; ++j)
            #pragma unroll
            for (int q = 0; q < 4; ++q) acc[i][j][q] = 0.0f;

    // ldmatrix lane addressing (constant per thread)
    const int a_row   = (lane & 7) + ((lane >> 3) & 1) * 8;   // +wm+mm*16
    const int a_chunk = (lane >> 4) & 1;                      // k 0-7 / 8-15
    const int b_k     = (lane & 7) + ((lane >> 3) & 1) * 8;
    const int b_nc8   = ((lane >> 4) & 1) * 8;                // +wn+nc*16

    // ---- prologue: fill stage 0 ----
    #pragma unroll
    for (int p = 0; p < 2; ++p) {
        int f  = tid + p * 256;                       // 0..511
        int ar = f >> 2, ac4 = f & 3;
        float4 av = *(const float4*)(Ab + (size_t)ar * K + ac4 * 4);
        *(uint2*)(&As[0][ar * GWA + 2 * ac4]) =
            make_uint2(pack_f16x2(av.x, av.y), pack_f16x2(av.z, av.w));
        int kr = f >> 5, cw = f & 31;
        float4 bv = *(const float4*)(Bb + (size_t)kr * N + cw * 4);
        *(uint2*)(&Bs[0][kr * GWB + 2 * cw]) =
            make_uint2(pack_f16x2(bv.x, bv.y), pack_f16x2(bv.z, bv.w));
    }

    int cur = 0;
    for (int kt = 0; kt < K; kt += 16) {
        __syncthreads();   // stage `cur` written; prev reads of `nxt` done

        const bool has_next = (kt + 16 < K);
        float4 areg[2], breg[2];
        if (has_next) {
            #pragma unroll
            for (int p = 0; p < 2; ++p) {
                int f  = tid + p * 256;
                int ar = f >> 2, ac4 = f & 3;
                areg[p] = *(const float4*)(Ab + (size_t)ar * K + kt + 16 + ac4 * 4);
                int kr = f >> 5, cw = f & 31;
                breg[p] = *(const float4*)(Bb + (size_t)(kt + 16 + kr) * N + cw * 4);
            }
        }

        // ---- compute on stage `cur` (one k16 step) ----
        {
            const uint32_t aBase = smem_u32(As[cur]);
            const uint32_t bBase = smem_u32(Bs[cur]);
            uint32_t a[2][4], b[8][2];
            #pragma unroll
            for (int mm = 0; mm < 2; ++mm) {
                uint32_t addr = aBase + (wm + mm * 16 + a_row) * 48 + a_chunk * 16;
                ldsm_x4(a[mm][0], a[mm][1], a[mm][2], a[mm][3], addr);
            }
            #pragma unroll
            for (int nc = 0; nc < 4; ++nc) {
                uint32_t addr = bBase + b_k * 272 + (wn + nc * 16 + b_nc8) * 2;
                uint32_t r0, r1, r2, r3;
                ldsm_x4_t(r0, r1, r2, r3, addr);
                b[2 * nc][0]     = r0; b[2 * nc][1]     = r1;
                b[2 * nc + 1][0] = r2; b[2 * nc + 1][1] = r3;
            }
            #pragma unroll
            for (int mm = 0; mm < 2; ++mm)
                #pragma unroll
                for (int nn = 0; nn < 8; ++nn)
                    mma_f16(acc[mm][nn], a[mm], b[nn]);
        }

        // ---- fill stage `nxt` ----
        if (has_next) {
            const int nxt = cur ^ 1;
            #pragma unroll
            for (int p = 0; p < 2; ++p) {
                int f  = tid + p * 256;
                int ar = f >> 2, ac4 = f & 3;
                *(uint2*)(&As[nxt][ar * GWA + 2 * ac4]) =
                    make_uint2(pack_f16x2(areg[p].x, areg[p].y),
                               pack_f16x2(areg[p].z, areg[p].w));
                int kr = f >> 5, cw = f & 31;
                *(uint2*)(&Bs[nxt][kr * GWB + 2 * cw]) =
                    make_uint2(pack_f16x2(breg[p].x, breg[p].y),
                               pack_f16x2(breg[p].z, breg[p].w));
            }
        }
        cur ^= 1;
    }

    // ---- epilogue: bias + store ----
    #pragma unroll
    for (int mm = 0; mm < 2; ++mm) {
        const int r0 = bm * 128 + wm + mm * 16 + g;
        #pragma unroll
        for (int nn = 0; nn < 8; ++nn) {
            const int c0g = bn * 128 + wn + nn * 8 + 2 * tg;
            float b0 = bias[c0g], b1 = bias[c0g + 1];
            float2 v0 = make_float2(acc[mm][nn][0] + b0, acc[mm][nn][1] + b1);
            float2 v1 = make_float2(acc[mm][nn][2] + b0, acc[mm][nn][3] + b1);
            *(float2*)(C + (size_t)r0 * N + c0g)       = v0;
            *(float2*)(C + (size_t)(r0 + 8) * N + c0g) = v1;
        }
    }
}

// ---------------------------------------------------------------------------
// Causal flash attention, fp16 m16n8k16, ldmatrix fragments.
// 128 threads = 4 warps. Q-tile 64 (16 rows/warp), K-tile 64, DH=64.
// K/V smem rows: 64 halves, stride 144B (9x16B; ldmatrix phases conflict-free).
// K-frags: ldmatrix.x4 (n8 x d32 per call). V-frags: ldmatrix.x4.trans
// (tok16 x d16 per call). P: C-frag -> A-frag in registers.
// ---------------------------------------------------------------------------
#define FWS 36    // K/V row stride in words (144B)

__global__ void __launch_bounds__(128, 3) flash_attn_f16_kernel()
{
    __shared__ __align__(16) uint32_t Ks[64 * FWS];   // Q staging, then K tiles
    __shared__ __align__(16) uint32_t Vs[64 * FWS];   // V tiles

    const int tid  = threadIdx.x;
    const int warp = tid >> 5;
    const int lane = tid & 31;
    const int g    = lane >> 2;
    const int tg   = lane & 3;
    const int qt   = gridDim.x - 1 - blockIdx.x;   // long diagonals first
    const int h    = blockIdx.y;
    const int b    = blockIdx.z;
    const int q0   = qt * 64;
    const int qrow = warp * 16;

    const float* qkv = g_qkv;
    const uint32_t ksBase = smem_u32(Ks);
    const uint32_t vsBase = smem_u32(Vs);

    // ldmatrix lane addressing (constant per thread)
    const int k_tok8  = lane & 7;                  // + n0*8
    const int k_doff  = ((lane >> 3) & 3) * 16;    // + dh*64
    const int v_tok   = (lane & 7) + ((lane >> 3) & 1) * 8;   // + kc*16
    const int v_dcol8 = ((lane >> 4) & 1) * 8;     // + dp*16

    // ---- stage Q (scaled by 1/8) into Ks; extract persistent A-frags ----
    #pragma unroll
    for (int p = 0; p < 8; ++p) {
        int idx = tid + p * 128;
        int r = idx >> 4, cp = idx & 15;
        float4 v = *(const float4*)(qkv + (size_t)(b * T_SEQ + q0 + r) * 3072 + h * 64 + cp * 4);
        *(uint2*)(&Ks[r * FWS + 2 * cp]) =
            make_uint2(pack_f16x2(v.x * 0.125f, v.y * 0.125f),
                       pack_f16x2(v.z * 0.125f, v.w * 0.125f));
    }
    __syncthreads();

    uint32_t aq[4][4];   // kc chunk = d 16kc..16kc+15
    #pragma unroll
    for (int kc = 0; kc < 2; ++kc) {
        // rows qrow..qrow+15, d 32kc..+31 (two x4 calls, 16B chunks)
        uint32_t addr = ksBase + (qrow + v_tok) * 144 + kc * 64 + v_dcol8 * 2;
        ldsm_x4(aq[2 * kc][0], aq[2 * kc][1], aq[2 * kc][2], aq[2 * kc][3], addr);
        uint32_t addr2 = addr + 32;
        ldsm_x4(aq[2 * kc + 1][0], aq[2 * kc + 1][1], aq[2 * kc + 1][2], aq[2 * kc + 1][3], addr2);
    }

    float oacc[8][4];
    #pragma unroll
    for (int i = 0; i < 8; ++i)
        #pragma unroll
        for (int j = 0; j < 4; ++j) oacc[i][j] = 0.0f;
    float mrow0 = -1e30f, mrow1 = -1e30f;
    float lrow0 = 0.0f,   lrow1 = 0.0f;

    const int nkt = qt + 1;
    for (int kt = 0; kt < nkt; ++kt) {
        const int k0 = kt * 64;

        __syncthreads();   // prior-iteration K/V reads done

        // ---- load K, V tiles as fp16 ----
        #pragma unroll
        for (int p = 0; p < 8; ++p) {
            int idx = tid + p * 128;
            int r = idx >> 4, cp = idx & 15;
            const float* base = qkv + (size_t)(b * T_SEQ + k0 + r) * 3072 + h * 64 + cp * 4;
            float4 kv = *(const float4*)(base + 1024);
            float4 vv = *(const float4*)(base + 2048);
            *(uint2*)(&Ks[r * FWS + 2 * cp]) =
                make_uint2(pack_f16x2(kv.x, kv.y), pack_f16x2(kv.z, kv.w));
            *(uint2*)(&Vs[r * FWS + 2 * cp]) =
                make_uint2(pack_f16x2(vv.x, vv.y), pack_f16x2(vv.z, vv.w));
        }
        __syncthreads();

        // ---- S = Q @ K^T  (per warp: 16x64; K-frags via ldmatrix.x4) ----
        float sacc[8][4];
        #pragma unroll
        for (int i = 0; i < 8; ++i)
            #pragma unroll
            for (int j = 0; j < 4; ++j) sacc[i][j] = 0.0f;

        #pragma unroll
        for (int n0 = 0; n0 < 8; ++n0) {
            #pragma unroll
            for (int dh = 0; dh < 2; ++dh) {
                uint32_t addr = ksBase + (n0 * 8 + k_tok8) * 144 + dh * 64 + k_doff;
                uint32_t r0, r1, r2, r3;
                ldsm_x4(r0, r1, r2, r3, addr);
                uint32_t bf0[2] = { r0, r1 };
                uint32_t bf1[2] = { r2, r3 };
                mma_f16(sacc[n0], aq[2 * dh],     bf0);
                mma_f16(sacc[n0], aq[2 * dh + 1], bf1);
            }
        }

        // ---- causal mask + row max (scale folded into Q) ----
        const int row0 = q0 + qrow + g;
        const int row1 = row0 + 8;
        const bool domask = (k0 + 63 > q0 + qrow);
        float ml0 = -1e30f, ml1 = -1e30f;
        #pragma unroll
        for (int n0 = 0; n0 < 8; ++n0) {
            const int c0 = k0 + n0 * 8 + 2 * tg;
            const int c1 = c0 + 1;
            float s0 = sacc[n0][0];
            float s1 = sacc[n0][1];
            float s2 = sacc[n0][2];
            float s3 = sacc[n0][3];
            if (domask) {
                if (c0 > row0) s0 = -1e30f;
                if (c1 > row0) s1 = -1e30f;
                if (c0 > row1) s2 = -1e30f;
                if (c1 > row1) s3 = -1e30f;
            }
            sacc[n0][0] = s0; sacc[n0][1] = s1;
            sacc[n0][2] = s2; sacc[n0][3] = s3;
            ml0 = fmaxf(ml0, fmaxf(s0, s1));
            ml1 = fmaxf(ml1, fmaxf(s2, s3));
        }
        ml0 = fmaxf(ml0, __shfl_xor_sync(0xffffffffu, ml0, 1));
        ml0 = fmaxf(ml0, __shfl_xor_sync(0xffffffffu, ml0, 2));
        ml1 = fmaxf(ml1, __shfl_xor_sync(0xffffffffu, ml1, 1));
        ml1 = fmaxf(ml1, __shfl_xor_sync(0xffffffffu, ml1, 2));

        const float nm0 = fmaxf(mrow0, ml0);
        const float nm1 = fmaxf(mrow1, ml1);
        const float al0 = __expf(mrow0 - nm0);
        const float al1 = __expf(mrow1 - nm1);
        mrow0 = nm0; mrow1 = nm1;

        float sum0 = 0.0f, sum1 = 0.0f;
        #pragma unroll
        for (int n0 = 0; n0 < 8; ++n0) {
            float p0 = __expf(sacc[n0][0] - nm0);
            float p1 = __expf(sacc[n0][1] - nm0);
            float p2 = __expf(sacc[n0][2] - nm1);
            float p3 = __expf(sacc[n0][3] - nm1);
            sacc[n0][0] = p0; sacc[n0][1] = p1;
            sacc[n0][2] = p2; sacc[n0][3] = p3;
            sum0 += p0 + p1;
            sum1 += p2 + p3;
        }
        sum0 += __shfl_xor_sync(0xffffffffu, sum0, 1);
        sum0 += __shfl_xor_sync(0xffffffffu, sum0, 2);
        sum1 += __shfl_xor_sync(0xffffffffu, sum1, 1);
        sum1 += __shfl_xor_sync(0xffffffffu, sum1, 2);
        lrow0 = lrow0 * al0 + sum0;
        lrow1 = lrow1 * al1 + sum1;

        #pragma unroll
        for (int n0 = 0; n0 < 8; ++n0) {
            oacc[n0][0] *= al0; oacc[n0][1] *= al0;
            oacc[n0][2] *= al1; oacc[n0][3] *= al1;
        }

        // ---- P: C-frag -> A-frag in registers ----
        uint32_t ap[4][4];
        #pragma unroll
        for (int kc = 0; kc < 4; ++kc) {
            ap[kc][0] = pack_f16x2(sacc[2 * kc][0],     sacc[2 * kc][1]);
            ap[kc][1] = pack_f16x2(sacc[2 * kc][2],     sacc[2 * kc][3]);
            ap[kc][2] = pack_f16x2(sacc[2 * kc + 1][0], sacc[2 * kc + 1][1]);
            ap[kc][3] = pack_f16x2(sacc[2 * kc + 1][2], sacc[2 * kc + 1][3]);
        }

        // ---- O += P @ V  (V-frags via ldmatrix.x4.trans) ----
        #pragma unroll
        for (int kc = 0; kc < 4; ++kc) {
            #pragma unroll
            for (int dp = 0; dp < 4; ++dp) {
                uint32_t addr = vsBase + (kc * 16 + v_tok) * 144 + (dp * 16 + v_dcol8) * 2;
                uint32_t r0, r1, r2, r3;
                ldsm_x4_t(r0, r1, r2, r3, addr);
                uint32_t bf0[2] = { r0, r1 };
                uint32_t bf1[2] = { r2, r3 };
                mma_f16(oacc[2 * dp],     ap[kc], bf0);
                mma_f16(oacc[2 * dp + 1], ap[kc], bf1);
            }
        }
    }

    // ---- epilogue: normalize, write [B*T, D_MODEL] ----
    const float li0 = 1.0f / lrow0;
    const float li1 = 1.0f / lrow1;
    const size_t grow0 = (size_t)(b * T_SEQ + q0 + qrow + g);
    const size_t grow1 = grow0 + 8;
    #pragma unroll
    for (int n0 = 0; n0 < 8; ++n0) {
        const int col = h * 64 + n0 * 8 + 2 * tg;
        *(float2*)(g_attn + grow0 * D_MODEL + col) =
            make_float2(oacc[n0][0] * li0, oacc[n0][1] * li0);
        *(float2*)(g_attn + grow1 * D_MODEL + col) =
            make_float2(oacc[n0][2] * li1, oacc[n0][3] * li1);
    }
}

// ---------------------------------------------------------------------------
// Harness entry. Inputs: x, w_qkv, b_qkv, w_out, b_out (all fp32).
// ---------------------------------------------------------------------------
extern "C" void kernel_launch(void* const* d_in, const int* in_sizes, int n_in,
                              void* d_out, int out_size)
{
    (void)in_sizes; (void)n_in; (void)out_size;
    const float* x     = (const float*)d_in[0];
    const float* w_qkv = (const float*)d_in[1];
    const float* b_qkv = (const float*)d_in[2];
    const float* w_out = (const float*)d_in[3];
    const float* b_out = (const float*)d_in[4];
    float* out = (float*)d_out;

    float* qkv_buf  = nullptr;
    float* attn_buf = nullptr;
    cudaGetSymbolAddress((void**)&qkv_buf, g_qkv);
    cudaGetSymbolAddress((void**)&attn_buf, g_attn);

    // 1) QKV projection: [4096,1024] @ [1024,3072] + b
    gemm_f16_kernel<N_TOK, 3 * D_MODEL, D_MODEL>
        <<<dim3((3 * D_MODEL) / 128, N_TOK / 128), 256>>>(x, w_qkv, b_qkv, qkv_buf);

    // 2) causal flash attention (fp16 tensor cores) -> [B, T, H*DH]
    flash_attn_f16_kernel<<<dim3(T_SEQ / 64, N_HEADS, B_SZ), 128>>>();

    // 3) output projection: [4096,1024] @ [1024,1024] + b
    gemm_f16_kernel<N_TOK, D_MODEL, D_MODEL>
        <<<dim3(D_MODEL / 128, N_TOK / 128), 256>>>(attn_buf, w_out, b_out, out);
}

// round 14
// speedup vs baseline: 2.0680x; 1.1429x over previous
#include <cuda_runtime.h>
#include <cuda_fp16.h>
#include <cstdint>

#define T_SEQ   2048
#define D_MODEL 1024
#define N_HEADS 16
#define D_HEAD  64
#define B_SZ    2
#define N_TOK   (B_SZ * T_SEQ)   // 4096

// fp16 scratch (device globals: allocation-free per harness rules)
__device__ __half g_xh  [(size_t)N_TOK * D_MODEL];        // x in fp16
__device__ __half g_wqh [(size_t)D_MODEL * 3 * D_MODEL];  // w_qkv fp16
__device__ __half g_woh [(size_t)D_MODEL * D_MODEL];      // w_out fp16
__device__ __half g_qkvh[(size_t)N_TOK * 3 * D_MODEL];    // qkv (Q pre-scaled 1/8)
__device__ __half g_atth[(size_t)N_TOK * D_MODEL];        // attention out fp16

// ---------------------------------------------------------------------------
// helpers
// ---------------------------------------------------------------------------
__device__ __forceinline__ uint32_t pack_f16x2(float lo, float hi) {
    uint32_t r;
    asm("cvt.rn.f16x2.f32 %0, %1, %2;" : "=r"(r) : "f"(hi), "f"(lo));
    return r;
}

__device__ __forceinline__ void mma_f16(float c[4], const uint32_t a[4], const uint32_t b[2]) {
    asm volatile(
        "mma.sync.aligned.m16n8k16.row.col.f32.f16.f16.f32 "
        "{%0,%1,%2,%3}, {%4,%5,%6,%7}, {%8,%9}, {%0,%1,%2,%3};\n"
        : "+f"(c[0]), "+f"(c[1]), "+f"(c[2]), "+f"(c[3])
        : "r"(a[0]), "r"(a[1]), "r"(a[2]), "r"(a[3]), "r"(b[0]), "r"(b[1]));
}

__device__ __forceinline__ uint32_t smem_u32(const void* p) {
    uint32_t a;
    asm("{ .reg .u64 t; cvta.to.shared.u64 t, %1; cvt.u32.u64 %0, t; }"
        : "=r"(a) : "l"(p));
    return a;
}

__device__ __forceinline__ void ldsm_x4(uint32_t& r0, uint32_t& r1,
                                        uint32_t& r2, uint32_t& r3, uint32_t addr) {
    asm volatile("ldmatrix.sync.aligned.m8n8.x4.shared.b16 {%0,%1,%2,%3}, [%4];"
                 : "=r"(r0), "=r"(r1), "=r"(r2), "=r"(r3) : "r"(addr));
}
__device__ __forceinline__ void ldsm_x4_t(uint32_t& r0, uint32_t& r1,
                                          uint32_t& r2, uint32_t& r3, uint32_t addr) {
    asm volatile("ldmatrix.sync.aligned.m8n8.x4.trans.shared.b16 {%0,%1,%2,%3}, [%4];"
                 : "=r"(r0), "=r"(r1), "=r"(r2), "=r"(r3) : "r"(addr));
}

__device__ __forceinline__ void cp16(uint32_t dst, const void* src) {
    asm volatile("cp.async.cg.shared.global [%0], [%1], 16;" :: "r"(dst), "l"(src));
}
#define CP_COMMIT() asm volatile("cp.async.commit_group;" ::: "memory")
#define CP_WAIT0()  asm volatile("cp.async.wait_group 0;" ::: "memory")
#define CP_WAIT1()  asm volatile("cp.async.wait_group 1;" ::: "memory")

// ---------------------------------------------------------------------------
// fp32 -> fp16 converter (elementwise, float4 -> 2x f16x2)
// ---------------------------------------------------------------------------
__global__ void cvt_f32_f16_kernel(const float4* __restrict__ in,
                                   uint2* __restrict__ out, int n4)
{
    int i = blockIdx.x * blockDim.x + threadIdx.x;
    if (i < n4) {
        float4 v = in[i];
        out[i] = make_uint2(pack_f16x2(v.x, v.y), pack_f16x2(v.z, v.w));
    }
}

// ---------------------------------------------------------------------------
// fp16-in tensor-core GEMM with fused bias, 3-stage cp.async pipeline.
// C[M,N] = A[M,K] @ B[K,N] + bias[N]. A,B fp16 row-major.
// OUTH=1: fp16 output, cols < q_cols additionally scaled by 1/8.
// OUTH=0: fp32 output.
// Block tile 128x128, ktile 16, 256 threads = 8 warps, warp tile 32x64.
// A smem rows stride 48B; B smem rows stride 272B (ldmatrix conflict-free).
// ---------------------------------------------------------------------------
#define GWA 12   // A row stride in words (48B)
#define GWB 68   // B row stride in words (272B)

template <int M, int N, int K, int OUTH>
__global__ void __launch_bounds__(256, 2) gemm_f16_kernel(
    const __half* __restrict__ A, const __half* __restrict__ B,
    const float* __restrict__ bias, void* __restrict__ Cout, int q_cols)
{
    __shared__ __align__(16) uint32_t As[3][128 * GWA];   // 6 KB/stage
    __shared__ __align__(16) uint32_t Bs[3][16 * GWB];    // 4.25 KB/stage

    const int tid  = threadIdx.x;
    const int warp = tid >> 5;
    const int lane = tid & 31;
    const int g    = lane >> 2;
    const int tg   = lane & 3;
    const int wm   = (warp >> 1) * 32;
    const int wn   = (warp & 1) * 64;

    const int bm = blockIdx.y;
    const int bn = blockIdx.x;

    const __half* Ab = A + (size_t)bm * 128 * K;
    const __half* Bb = B + (size_t)bn * 128;

    // cp.async mappings: A 128r x 32B (2 chunks/row); B 16k x 256B (16 chunks/row)
    const int a_r = tid >> 1, a_c = tid & 1;
    const int b_r = tid >> 4, b_c = tid & 15;

    float acc[2][8][4];
    #pragma unroll
    for (int i = 0; i < 2; ++i)
        #pragma unroll
        for (int j = 0; j < 8; ++j)
            #pragma unroll
            for (int q = 0; q < 4; ++q) acc[i][j][q] = 0.0f;

    // ldmatrix lane addressing
    const int a_row   = (lane & 7) + ((lane >> 3) & 1) * 8;
    const int a_chunk = (lane >> 4) & 1;
    const int b_k     = (lane & 7) + ((lane >> 3) & 1) * 8;
    const int b_nc8   = ((lane >> 4) & 1) * 8;

    const int NKT = K / 16;

    // issue stage st covering k-offset kt
    #define GISSUE(st, kt) do {                                                   \
        uint32_t ad = smem_u32(&As[st][0]) + a_r * 48 + a_c * 16;                 \
        cp16(ad, Ab + (size_t)a_r * K + (kt) + a_c * 8);                          \
        uint32_t bd = smem_u32(&Bs[st][0]) + b_r * 272 + b_c * 16;                \
        cp16(bd, Bb + (size_t)((kt) + b_r) * N + b_c * 8);                        \
        CP_COMMIT();                                                              \
    } while (0)

    GISSUE(0, 0);
    GISSUE(1, 16);          // K >= 32 always here

    for (int kt = 0; kt < NKT; ++kt) {
        const int cur = kt % 3;
        if (kt + 1 < NKT) CP_WAIT1(); else CP_WAIT0();
        __syncthreads();    // stage cur visible to all; all done computing kt-1
        if (kt + 2 < NKT) GISSUE((kt + 2) % 3, (kt + 2) * 16);

        const uint32_t aBase = smem_u32(&As[cur][0]);
        const uint32_t bBase = smem_u32(&Bs[cur][0]);
        uint32_t a[2][4], b[8][2];
        #pragma unroll
        for (int mm = 0; mm < 2; ++mm) {
            uint32_t addr = aBase + (wm + mm * 16 + a_row) * 48 + a_chunk * 16;
            ldsm_x4(a[mm][0], a[mm][1], a[mm][2], a[mm][3], addr);
        }
        #pragma unroll
        for (int nc = 0; nc < 4; ++nc) {
            uint32_t addr = bBase + b_k * 272 + (wn + nc * 16 + b_nc8) * 2;
            uint32_t r0, r1, r2, r3;
            ldsm_x4_t(r0, r1, r2, r3, addr);
            b[2 * nc][0]     = r0; b[2 * nc][1]     = r1;
            b[2 * nc + 1][0] = r2; b[2 * nc + 1][1] = r3;
        }
        #pragma unroll
        for (int mm = 0; mm < 2; ++mm)
            #pragma unroll
            for (int nn = 0; nn < 8; ++nn)
                mma_f16(acc[mm][nn], a[mm], b[nn]);
    }
    #undef GISSUE

    // ---- epilogue ----
    #pragma unroll
    for (int mm = 0; mm < 2; ++mm) {
        const int r0 = bm * 128 + wm + mm * 16 + g;
        #pragma unroll
        for (int nn = 0; nn < 8; ++nn) {
            const int c0g = bn * 128 + wn + nn * 8 + 2 * tg;
            float b0 = bias[c0g], b1 = bias[c0g + 1];
            if (OUTH) {
                __half* C = (__half*)Cout;
                float sc = (c0g < q_cols) ? 0.125f : 1.0f;
                *(uint32_t*)(C + (size_t)r0 * N + c0g) =
                    pack_f16x2((acc[mm][nn][0] + b0) * sc, (acc[mm][nn][1] + b1) * sc);
                *(uint32_t*)(C + (size_t)(r0 + 8) * N + c0g) =
                    pack_f16x2((acc[mm][nn][2] + b0) * sc, (acc[mm][nn][3] + b1) * sc);
            } else {
                float* C = (float*)Cout;
                *(float2*)(C + (size_t)r0 * N + c0g) =
                    make_float2(acc[mm][nn][0] + b0, acc[mm][nn][1] + b1);
                *(float2*)(C + (size_t)(r0 + 8) * N + c0g) =
                    make_float2(acc[mm][nn][2] + b0, acc[mm][nn][3] + b1);
            }
        }
    }
}

// ---------------------------------------------------------------------------
// Causal flash attention, fp16 m16n8k16, ldmatrix frags, cp.async loads.
// Q pre-scaled by 1/8 in g_qkvh. K/V rows: 64 halves = 128B data, stride 144B.
// Output fp16 to g_atth.
// ---------------------------------------------------------------------------
#define FWS 36    // K/V row stride in words (144B)

__global__ void __launch_bounds__(128, 3) flash_attn_f16_kernel()
{
    __shared__ __align__(16) uint32_t Ks[64 * FWS];
    __shared__ __align__(16) uint32_t Vs[64 * FWS];

    const int tid  = threadIdx.x;
    const int warp = tid >> 5;
    const int lane = tid & 31;
    const int g    = lane >> 2;
    const int tg   = lane & 3;
    const int qt   = gridDim.x - 1 - blockIdx.x;   // long diagonals first
    const int h    = blockIdx.y;
    const int b    = blockIdx.z;
    const int q0   = qt * 64;
    const int qrow = warp * 16;

    const __half* qkvh = g_qkvh;
    const uint32_t ksBase = smem_u32(Ks);
    const uint32_t vsBase = smem_u32(Vs);

    // ldmatrix lane addressing
    const int k_tok8  = lane & 7;
    const int k_doff  = ((lane >> 3) & 3) * 16;
    const int v_tok   = (lane & 7) + ((lane >> 3) & 1) * 8;
    const int v_dcol8 = ((lane >> 4) & 1) * 8;

    // ---- stage Q (already scaled) into Ks via cp.async ----
    #pragma unroll
    for (int p = 0; p < 4; ++p) {
        int idx = tid + p * 128;           // 0..511
        int r = idx >> 3, c = idx & 7;     // row, 16B chunk
        cp16(ksBase + r * 144 + c * 16,
             qkvh + (size_t)(b * T_SEQ + q0 + r) * 3072 + h * 64 + c * 8);
    }
    CP_COMMIT(); CP_WAIT0();
    __syncthreads();

    uint32_t aq[4][4];
    #pragma unroll
    for (int kc = 0; kc < 2; ++kc) {
        uint32_t addr = ksBase + (qrow + v_tok) * 144 + kc * 64 + v_dcol8 * 2;
        ldsm_x4(aq[2 * kc][0], aq[2 * kc][1], aq[2 * kc][2], aq[2 * kc][3], addr);
        uint32_t addr2 = addr + 32;
        ldsm_x4(aq[2 * kc + 1][0], aq[2 * kc + 1][1], aq[2 * kc + 1][2], aq[2 * kc + 1][3], addr2);
    }

    float oacc[8][4];
    #pragma unroll
    for (int i = 0; i < 8; ++i)
        #pragma unroll
        for (int j = 0; j < 4; ++j) oacc[i][j] = 0.0f;
    float mrow0 = -1e30f, mrow1 = -1e30f;
    float lrow0 = 0.0f,   lrow1 = 0.0f;

    const int nkt = qt + 1;
    for (int kt = 0; kt < nkt; ++kt) {
        const int k0 = kt * 64;

        __syncthreads();   // prior-iteration K/V reads (and Q frag extraction) done

        // ---- load K, V tiles via cp.async (no conversion!) ----
        #pragma unroll
        for (int p = 0; p < 4; ++p) {
            int idx = tid + p * 128;
            int r = idx >> 3, c = idx & 7;
            const __half* base = qkvh + (size_t)(b * T_SEQ + k0 + r) * 3072 + h * 64 + c * 8;
            cp16(ksBase + r * 144 + c * 16, base + 1024);
            cp16(vsBase + r * 144 + c * 16, base + 2048);
        }
        CP_COMMIT(); CP_WAIT0();
        __syncthreads();

        // ---- S = Q @ K^T ----
        float sacc[8][4];
        #pragma unroll
        for (int i = 0; i < 8; ++i)
            #pragma unroll
            for (int j = 0; j < 4; ++j) sacc[i][j] = 0.0f;

        #pragma unroll
        for (int n0 = 0; n0 < 8; ++n0) {
            #pragma unroll
            for (int dh = 0; dh < 2; ++dh) {
                uint32_t addr = ksBase + (n0 * 8 + k_tok8) * 144 + dh * 64 + k_doff;
                uint32_t r0, r1, r2, r3;
                ldsm_x4(r0, r1, r2, r3, addr);
                uint32_t bf0[2] = { r0, r1 };
                uint32_t bf1[2] = { r2, r3 };
                mma_f16(sacc[n0], aq[2 * dh],     bf0);
                mma_f16(sacc[n0], aq[2 * dh + 1], bf1);
            }
        }

        // ---- causal mask + row max ----
        const int row0 = q0 + qrow + g;
        const int row1 = row0 + 8;
        const bool domask = (k0 + 63 > q0 + qrow);
        float ml0 = -1e30f, ml1 = -1e30f;
        #pragma unroll
        for (int n0 = 0; n0 < 8; ++n0) {
            const int c0 = k0 + n0 * 8 + 2 * tg;
            const int c1 = c0 + 1;
            float s0 = sacc[n0][0];
            float s1 = sacc[n0][1];
            float s2 = sacc[n0][2];
            float s3 = sacc[n0][3];
            if (domask) {
                if (c0 > row0) s0 = -1e30f;
                if (c1 > row0) s1 = -1e30f;
                if (c0 > row1) s2 = -1e30f;
                if (c1 > row1) s3 = -1e30f;
            }
            sacc[n0][0] = s0; sacc[n0][1] = s1;
            sacc[n0][2] = s2; sacc[n0][3] = s3;
            ml0 = fmaxf(ml0, fmaxf(s0, s1));
            ml1 = fmaxf(ml1, fmaxf(s2, s3));
        }
        ml0 = fmaxf(ml0, __shfl_xor_sync(0xffffffffu, ml0, 1));
        ml0 = fmaxf(ml0, __shfl_xor_sync(0xffffffffu, ml0, 2));
        ml1 = fmaxf(ml1, __shfl_xor_sync(0xffffffffu, ml1, 1));
        ml1 = fmaxf(ml1, __shfl_xor_sync(0xffffffffu, ml1, 2));

        const float nm0 = fmaxf(mrow0, ml0);
        const float nm1 = fmaxf(mrow1, ml1);
        const float al0 = __expf(mrow0 - nm0);
        const float al1 = __expf(mrow1 - nm1);
        mrow0 = nm0; mrow1 = nm1;

        float sum0 = 0.0f, sum1 = 0.0f;
        #pragma unroll
        for (int n0 = 0; n0 < 8; ++n0) {
            float p0 = __expf(sacc[n0][0] - nm0);
            float p1 = __expf(sacc[n0][1] - nm0);
            float p2 = __expf(sacc[n0][2] - nm1);
            float p3 = __expf(sacc[n0][3] - nm1);
            sacc[n0][0] = p0; sacc[n0][1] = p1;
            sacc[n0][2] = p2; sacc[n0][3] = p3;
            sum0 += p0 + p1;
            sum1 += p2 + p3;
        }
        sum0 += __shfl_xor_sync(0xffffffffu, sum0, 1);
        sum0 += __shfl_xor_sync(0xffffffffu, sum0, 2);
        sum1 += __shfl_xor_sync(0xffffffffu, sum1, 1);
        sum1 += __shfl_xor_sync(0xffffffffu, sum1, 2);
        lrow0 = lrow0 * al0 + sum0;
        lrow1 = lrow1 * al1 + sum1;

        #pragma unroll
        for (int n0 = 0; n0 < 8; ++n0) {
            oacc[n0][0] *= al0; oacc[n0][1] *= al0;
            oacc[n0][2] *= al1; oacc[n0][3] *= al1;
        }

        // ---- P: C-frag -> A-frag in registers ----
        uint32_t ap[4][4];
        #pragma unroll
        for (int kc = 0; kc < 4; ++kc) {
            ap[kc][0] = pack_f16x2(sacc[2 * kc][0],     sacc[2 * kc][1]);
            ap[kc][1] = pack_f16x2(sacc[2 * kc][2],     sacc[2 * kc][3]);
            ap[kc][2] = pack_f16x2(sacc[2 * kc + 1][0], sacc[2 * kc + 1][1]);
            ap[kc][3] = pack_f16x2(sacc[2 * kc + 1][2], sacc[2 * kc + 1][3]);
        }

        // ---- O += P @ V ----
        #pragma unroll
        for (int kc = 0; kc < 4; ++kc) {
            #pragma unroll
            for (int dp = 0; dp < 4; ++dp) {
                uint32_t addr = vsBase + (kc * 16 + v_tok) * 144 + (dp * 16 + v_dcol8) * 2;
                uint32_t r0, r1, r2, r3;
                ldsm_x4_t(r0, r1, r2, r3, addr);
                uint32_t bf0[2] = { r0, r1 };
                uint32_t bf1[2] = { r2, r3 };
                mma_f16(oacc[2 * dp],     ap[kc], bf0);
                mma_f16(oacc[2 * dp + 1], ap[kc], bf1);
            }
        }
    }

    // ---- epilogue: normalize, write fp16 [B*T, D_MODEL] ----
    const float li0 = 1.0f / lrow0;
    const float li1 = 1.0f / lrow1;
    __half* atth = g_atth;
    const size_t grow0 = (size_t)(b * T_SEQ + q0 + qrow + g);
    const size_t grow1 = grow0 + 8;
    #pragma unroll
    for (int n0 = 0; n0 < 8; ++n0) {
        const int col = h * 64 + n0 * 8 + 2 * tg;
        *(uint32_t*)(atth + grow0 * D_MODEL + col) =
            pack_f16x2(oacc[n0][0] * li0, oacc[n0][1] * li0);
        *(uint32_t*)(atth + grow1 * D_MODEL + col) =
            pack_f16x2(oacc[n0][2] * li1, oacc[n0][3] * li1);
    }
}

// ---------------------------------------------------------------------------
// Harness entry. Inputs: x, w_qkv, b_qkv, w_out, b_out (all fp32).
// ---------------------------------------------------------------------------
extern "C" void kernel_launch(void* const* d_in, const int* in_sizes, int n_in,
                              void* d_out, int out_size)
{
    (void)in_sizes; (void)n_in; (void)out_size;
    const float* x     = (const float*)d_in[0];
    const float* w_qkv = (const float*)d_in[1];
    const float* b_qkv = (const float*)d_in[2];
    const float* w_out = (const float*)d_in[3];
    const float* b_out = (const float*)d_in[4];
    float* out = (float*)d_out;

    __half *xh, *wqh, *woh, *qkvh, *atth;
    cudaGetSymbolAddress((void**)&xh,   g_xh);
    cudaGetSymbolAddress((void**)&wqh,  g_wqh);
    cudaGetSymbolAddress((void**)&woh,  g_woh);
    cudaGetSymbolAddress((void**)&qkvh, g_qkvh);
    cudaGetSymbolAddress((void**)&atth, g_atth);

    // 0) fp32 -> fp16 pre-conversion (one-time per launch)
    {
        const int nx = N_TOK * D_MODEL / 4;          // 1M float4
        const int nw = D_MODEL * 3 * D_MODEL / 4;    // 768K
        const int no = D_MODEL * D_MODEL / 4;        // 256K
        cvt_f32_f16_kernel<<<(nx + 255) / 256, 256>>>((const float4*)x,     (uint2*)xh,  nx);
        cvt_f32_f16_kernel<<<(nw + 255) / 256, 256>>>((const float4*)w_qkv, (uint2*)wqh, nw);
        cvt_f32_f16_kernel<<<(no + 255) / 256, 256>>>((const float4*)w_out, (uint2*)woh, no);
    }

    // 1) QKV projection (fp16 out, Q columns pre-scaled by 1/8)
    gemm_f16_kernel<N_TOK, 3 * D_MODEL, D_MODEL, 1>
        <<<dim3((3 * D_MODEL) / 128, N_TOK / 128), 256>>>(xh, wqh, b_qkv, qkvh, D_MODEL);

    // 2) causal flash attention -> g_atth (fp16)
    flash_attn_f16_kernel<<<dim3(T_SEQ / 64, N_HEADS, B_SZ), 128>>>();

    // 3) output projection (fp32 out)
    gemm_f16_kernel<N_TOK, D_MODEL, D_MODEL, 0>
        <<<dim3(D_MODEL / 128, N_TOK / 128), 256>>>(atth, woh, b_out, out, 0);
}